// round 1
// baseline (speedup 1.0000x reference)
#include <cuda_runtime.h>
#include <math_constants.h>

#define NB 32
#define NC 256
#define HW 1024

static __device__ __constant__ float c_invT = 14.2857142857142857f; // 1/0.07

// Scratch (device globals; no allocation allowed)
__device__ float g_Aperm[(size_t)NB * NC * HW];        // 33.5 MB
__device__ float g_L[(size_t)NB * HW * HW];            // 134 MB
__device__ float g_rmax[NB * HW];
__device__ float g_rinv[NB * HW];
__device__ float g_cmax[NB * HW];
__device__ float g_cinv[NB * HW];

// ---------------------------------------------------------------------------
// Kernel 1: per-(b,c) 32x32 plane transpose: A_perm[p][wi*32+hi] = A[p][hi*32+wi]
// ---------------------------------------------------------------------------
__global__ void transpose_planes_kernel(const float* __restrict__ A) {
    __shared__ float s[32][33];
    int plane = blockIdx.x;                 // b*NC + c
    const float* src = A + (size_t)plane * 1024;
    float* dst = g_Aperm + (size_t)plane * 1024;
    int t = threadIdx.x;
    int col = t & 31;
    int row0 = t >> 5;                      // 0..7
#pragma unroll
    for (int r = 0; r < 4; r++) {
        int row = row0 + r * 8;
        s[row][col] = src[row * 32 + col];
    }
    __syncthreads();
#pragma unroll
    for (int r = 0; r < 4; r++) {
        int row = row0 + r * 8;
        dst[row * 32 + col] = s[col][row];
    }
}

// ---------------------------------------------------------------------------
// Kernel 2: batched SGEMM. L[b][i][j] = invT * sum_k B[b][k][i] * Aperm[b][k][j]
// Both operands are K-major [256][1024]. 128x128 tile, K-chunk 8, 8x8/thread.
// ---------------------------------------------------------------------------
__global__ __launch_bounds__(256) void sgemm_kernel(const float* __restrict__ Bf) {
    int b = blockIdx.z;
    const float* Bp = Bf + (size_t)b * NC * HW;        // [k][i]
    const float* Ap = g_Aperm + (size_t)b * NC * HW;   // [k][j]
    float* Lp = g_L + (size_t)b * HW * HW;

    int i0 = blockIdx.y * 128;
    int j0 = blockIdx.x * 128;

    __shared__ float sB[8][128];
    __shared__ float sA[8][128];

    int t  = threadIdx.x;
    int lr = t >> 5;               // load row within k-chunk (0..7)
    int lc = (t & 31) << 2;        // load col (float4)
    int tx = (t & 15) << 3;        // j micro-tile offset (0..120)
    int ty = (t >> 4) << 3;        // i micro-tile offset (0..120)

    float acc[8][8];
#pragma unroll
    for (int ii = 0; ii < 8; ii++)
#pragma unroll
        for (int jj = 0; jj < 8; jj++) acc[ii][jj] = 0.0f;

    const float* gB = Bp + lr * HW + i0 + lc;
    const float* gA = Ap + lr * HW + j0 + lc;

    for (int k0 = 0; k0 < NC; k0 += 8) {
        float4 vb = *(const float4*)(gB + (size_t)k0 * HW);
        float4 va = *(const float4*)(gA + (size_t)k0 * HW);
        __syncthreads();
        *(float4*)&sB[lr][lc] = vb;
        *(float4*)&sA[lr][lc] = va;
        __syncthreads();
#pragma unroll
        for (int kk = 0; kk < 8; kk++) {
            float rb[8], ra[8];
            *(float4*)(rb)     = *(const float4*)&sB[kk][ty];
            *(float4*)(rb + 4) = *(const float4*)&sB[kk][ty + 4];
            *(float4*)(ra)     = *(const float4*)&sA[kk][tx];
            *(float4*)(ra + 4) = *(const float4*)&sA[kk][tx + 4];
#pragma unroll
            for (int ii = 0; ii < 8; ii++)
#pragma unroll
                for (int jj = 0; jj < 8; jj++)
                    acc[ii][jj] = fmaf(rb[ii], ra[jj], acc[ii][jj]);
        }
    }

    const float invT = c_invT;
#pragma unroll
    for (int ii = 0; ii < 8; ii++) {
        float* dst = Lp + (size_t)(i0 + ty + ii) * HW + j0 + tx;
        float4 o0, o1;
        o0.x = acc[ii][0] * invT; o0.y = acc[ii][1] * invT;
        o0.z = acc[ii][2] * invT; o0.w = acc[ii][3] * invT;
        o1.x = acc[ii][4] * invT; o1.y = acc[ii][5] * invT;
        o1.z = acc[ii][6] * invT; o1.w = acc[ii][7] * invT;
        *(float4*)(dst)     = o0;
        *(float4*)(dst + 4) = o1;
    }
}

// ---------------------------------------------------------------------------
// Kernel 3: row stats (reduce over j, contiguous). One warp per row.
// ---------------------------------------------------------------------------
__global__ void row_stats_kernel() {
    int gw   = (blockIdx.x * blockDim.x + threadIdx.x) >> 5; // row index (b*HW+i)
    int lane = threadIdx.x & 31;
    if (gw >= NB * HW) return;
    const float* row = g_L + (size_t)gw * HW;

    float m = -CUDART_INF_F;
#pragma unroll
    for (int it = 0; it < 8; it++) {
        float4 x = *(const float4*)(row + it * 128 + lane * 4);
        m = fmaxf(m, fmaxf(fmaxf(x.x, x.y), fmaxf(x.z, x.w)));
    }
#pragma unroll
    for (int off = 16; off > 0; off >>= 1)
        m = fmaxf(m, __shfl_xor_sync(0xFFFFFFFFu, m, off));

    float s = 0.0f;
#pragma unroll
    for (int it = 0; it < 8; it++) {
        float4 x = *(const float4*)(row + it * 128 + lane * 4);
        s += __expf(x.x - m) + __expf(x.y - m) + __expf(x.z - m) + __expf(x.w - m);
    }
#pragma unroll
    for (int off = 16; off > 0; off >>= 1)
        s += __shfl_xor_sync(0xFFFFFFFFu, s, off);

    if (lane == 0) {
        g_rmax[gw] = m;
        g_rinv[gw] = 1.0f / s;
    }
}

// ---------------------------------------------------------------------------
// Kernel 4: col stats (reduce over i, stride HW). Thread-per-j, coalesced,
// online softmax, i unrolled x4 for MLP.
// ---------------------------------------------------------------------------
__global__ void col_stats_kernel() {
    int b = blockIdx.y;
    int j = blockIdx.x * 256 + threadIdx.x;
    const float* Lp = g_L + (size_t)b * HW * HW + j;

    float m = -CUDART_INF_F;
    float s = 0.0f;
    for (int i = 0; i < HW; i += 4) {
        float x0 = Lp[(size_t)(i + 0) * HW];
        float x1 = Lp[(size_t)(i + 1) * HW];
        float x2 = Lp[(size_t)(i + 2) * HW];
        float x3 = Lp[(size_t)(i + 3) * HW];
        float mx = fmaxf(fmaxf(x0, x1), fmaxf(x2, x3));
        if (mx > m) {
            s *= __expf(m - mx);
            m = mx;
        }
        s += __expf(x0 - m) + __expf(x1 - m) + __expf(x2 - m) + __expf(x3 - m);
    }
    g_cmax[b * HW + j] = m;
    g_cinv[b * HW + j] = 1.0f / s;
}

// ---------------------------------------------------------------------------
// Kernel 5: out[b][j][i] = exp(2L[i][j] - rmax[i] - cmax[j]) * rinv[i]*cinv[j]
// 32x32 smem tile transpose; coalesced read (j) and write (i).
// ---------------------------------------------------------------------------
__global__ void out_kernel(float* __restrict__ out) {
    __shared__ float s[32][33];
    int b  = blockIdx.z;
    int i0 = blockIdx.y * 32;
    int j0 = blockIdx.x * 32;
    int tx = threadIdx.x;   // 0..31
    int ty = threadIdx.y;   // 0..7

    const float* Lp = g_L + (size_t)b * HW * HW;
#pragma unroll
    for (int r = 0; r < 4; r++) {
        int il = ty + r * 8;
        s[il][tx] = Lp[(size_t)(i0 + il) * HW + j0 + tx];
    }
    __syncthreads();

    int i = i0 + tx;
    float rm = g_rmax[b * HW + i];
    float ri = g_rinv[b * HW + i];
    float* op = out + (size_t)b * HW * HW;
#pragma unroll
    for (int r = 0; r < 4; r++) {
        int jl = ty + r * 8;
        int j  = j0 + jl;
        float cm = g_cmax[b * HW + j];
        float ci = g_cinv[b * HW + j];
        float v  = __expf(2.0f * s[tx][jl] - rm - cm) * (ri * ci);
        op[(size_t)j * HW + i] = v;
    }
}

// ---------------------------------------------------------------------------
extern "C" void kernel_launch(void* const* d_in, const int* in_sizes, int n_in,
                              void* d_out, int out_size) {
    const float* A  = (const float*)d_in[0];  // feature_A [32,256,32,32]
    const float* Bf = (const float*)d_in[1];  // feature_B [32,256,32,32]
    float* out = (float*)d_out;               // [32,1024,32,32]

    transpose_planes_kernel<<<NB * NC, 256>>>(A);
    sgemm_kernel<<<dim3(8, 8, NB), 256>>>(Bf);
    row_stats_kernel<<<(NB * HW) / 8, 256>>>();
    col_stats_kernel<<<dim3(HW / 256, NB), 256>>>();
    out_kernel<<<dim3(32, 32, NB), dim3(32, 8)>>>(out);
}

// round 2
// speedup vs baseline: 1.1509x; 1.1509x over previous
#include <cuda_runtime.h>
#include <math_constants.h>

#define NB 32
#define NC 256
#define HW 1024
#define NCHUNK 8          // i-chunks for col stats
#define CHUNK_I (HW / NCHUNK)

static __device__ __constant__ float c_invT = 14.2857142857142857f; // 1/0.07

// Scratch (device globals; no allocation allowed)
__device__ float g_Aperm[(size_t)NB * NC * HW];        // 33.5 MB
__device__ float g_L[(size_t)NB * HW * HW];            // 134 MB
__device__ float g_rmax[NB * HW];
__device__ float g_rinv[NB * HW];
__device__ float g_cmax[NB * HW];
__device__ float g_cinv[NB * HW];
__device__ float g_pm[NCHUNK * NB * HW];               // partial col max
__device__ float g_ps[NCHUNK * NB * HW];               // partial col sum

// ---- f32x2 helpers (PTX ISA 8.6, sm_100+) ---------------------------------
__device__ __forceinline__ unsigned long long pack2(float x, float y) {
    unsigned long long r;
    asm("mov.b64 %0, {%1, %2};" : "=l"(r) : "f"(x), "f"(y));
    return r;
}
__device__ __forceinline__ unsigned long long fma2(unsigned long long a,
                                                   unsigned long long b,
                                                   unsigned long long c) {
    unsigned long long d;
    asm("fma.rn.f32x2 %0, %1, %2, %3;" : "=l"(d) : "l"(a), "l"(b), "l"(c));
    return d;
}
__device__ __forceinline__ unsigned long long mul2(unsigned long long a,
                                                   unsigned long long b) {
    unsigned long long d;
    asm("mul.rn.f32x2 %0, %1, %2;" : "=l"(d) : "l"(a), "l"(b));
    return d;
}

// ---------------------------------------------------------------------------
// Kernel 1: per-(b,c) 32x32 plane transpose
// ---------------------------------------------------------------------------
__global__ void transpose_planes_kernel(const float* __restrict__ A) {
    __shared__ float s[32][33];
    int plane = blockIdx.x;                 // b*NC + c
    const float* src = A + (size_t)plane * 1024;
    float* dst = g_Aperm + (size_t)plane * 1024;
    int t = threadIdx.x;
    int col = t & 31;
    int row0 = t >> 5;                      // 0..7
#pragma unroll
    for (int r = 0; r < 4; r++) {
        int row = row0 + r * 8;
        s[row][col] = src[row * 32 + col];
    }
    __syncthreads();
#pragma unroll
    for (int r = 0; r < 4; r++) {
        int row = row0 + r * 8;
        dst[row * 32 + col] = s[col][row];
    }
}

// ---------------------------------------------------------------------------
// Kernel 2: batched SGEMM with packed f32x2 FMA.
// L[b][i][j] = invT * sum_k B[b][k][i] * Aperm[b][k][j]
// 128x128 tile, K-chunk 8, 8x8 per-thread micro-tile (acc held as 8x4 f32x2).
// ---------------------------------------------------------------------------
__global__ __launch_bounds__(256) void sgemm_kernel(const float* __restrict__ Bf) {
    int b = blockIdx.z;
    const float* Bp = Bf + (size_t)b * NC * HW;        // [k][i]
    const float* Ap = g_Aperm + (size_t)b * NC * HW;   // [k][j]
    float* Lp = g_L + (size_t)b * HW * HW;

    int i0 = blockIdx.y * 128;
    int j0 = blockIdx.x * 128;

    __shared__ float sB[8][128];
    __shared__ float sA[8][128];

    int t  = threadIdx.x;
    int lr = t >> 5;               // load row within k-chunk (0..7)
    int lc = (t & 31) << 2;        // load col (float4)
    int tx = (t & 15) << 3;        // j micro-tile offset (0..120)
    int ty = (t >> 4) << 3;        // i micro-tile offset (0..120)

    unsigned long long acc[8][4];
#pragma unroll
    for (int ii = 0; ii < 8; ii++)
#pragma unroll
        for (int j2 = 0; j2 < 4; j2++) acc[ii][j2] = 0ull;

    const float* gB = Bp + lr * HW + i0 + lc;
    const float* gA = Ap + lr * HW + j0 + lc;

    for (int k0 = 0; k0 < NC; k0 += 8) {
        float4 vb = *(const float4*)(gB + (size_t)k0 * HW);
        float4 va = *(const float4*)(gA + (size_t)k0 * HW);
        __syncthreads();
        *(float4*)&sB[lr][lc] = vb;
        *(float4*)&sA[lr][lc] = va;
        __syncthreads();
#pragma unroll
        for (int kk = 0; kk < 8; kk++) {
            float4 b0 = *(const float4*)&sB[kk][ty];
            float4 b1 = *(const float4*)&sB[kk][ty + 4];
            ulonglong2 a0 = *(const ulonglong2*)&sA[kk][tx];
            ulonglong2 a1 = *(const ulonglong2*)&sA[kk][tx + 4];
            unsigned long long ra2[4] = {a0.x, a0.y, a1.x, a1.y};
            float rbv[8] = {b0.x, b0.y, b0.z, b0.w, b1.x, b1.y, b1.z, b1.w};
#pragma unroll
            for (int ii = 0; ii < 8; ii++) {
                unsigned long long rb2 = pack2(rbv[ii], rbv[ii]);
#pragma unroll
                for (int j2 = 0; j2 < 4; j2++)
                    acc[ii][j2] = fma2(ra2[j2], rb2, acc[ii][j2]);
            }
        }
    }

    unsigned long long invT2 = pack2(c_invT, c_invT);
#pragma unroll
    for (int ii = 0; ii < 8; ii++) {
        float* dst = Lp + (size_t)(i0 + ty + ii) * HW + j0 + tx;
        ulonglong2 o0, o1;
        o0.x = mul2(acc[ii][0], invT2);
        o0.y = mul2(acc[ii][1], invT2);
        o1.x = mul2(acc[ii][2], invT2);
        o1.y = mul2(acc[ii][3], invT2);
        *(ulonglong2*)(dst)     = o0;
        *(ulonglong2*)(dst + 4) = o1;
    }
}

// ---------------------------------------------------------------------------
// Kernel 3: row stats (reduce over j, contiguous). One warp per row.
// ---------------------------------------------------------------------------
__global__ void row_stats_kernel() {
    int gw   = (blockIdx.x * blockDim.x + threadIdx.x) >> 5; // row index (b*HW+i)
    int lane = threadIdx.x & 31;
    if (gw >= NB * HW) return;
    const float* row = g_L + (size_t)gw * HW;

    float m = -CUDART_INF_F;
#pragma unroll
    for (int it = 0; it < 8; it++) {
        float4 x = *(const float4*)(row + it * 128 + lane * 4);
        m = fmaxf(m, fmaxf(fmaxf(x.x, x.y), fmaxf(x.z, x.w)));
    }
#pragma unroll
    for (int off = 16; off > 0; off >>= 1)
        m = fmaxf(m, __shfl_xor_sync(0xFFFFFFFFu, m, off));

    float s = 0.0f;
#pragma unroll
    for (int it = 0; it < 8; it++) {
        float4 x = *(const float4*)(row + it * 128 + lane * 4);
        s += __expf(x.x - m) + __expf(x.y - m) + __expf(x.z - m) + __expf(x.w - m);
    }
#pragma unroll
    for (int off = 16; off > 0; off >>= 1)
        s += __shfl_xor_sync(0xFFFFFFFFu, s, off);

    if (lane == 0) {
        g_rmax[gw] = m;
        g_rinv[gw] = 1.0f / s;
    }
}

// ---------------------------------------------------------------------------
// Kernel 4a: partial col stats. Each block covers 256 j's x 128 i's.
// grid (HW/256, NCHUNK, NB)
// ---------------------------------------------------------------------------
__global__ void col_stats_part_kernel() {
    int b     = blockIdx.z;
    int chunk = blockIdx.y;
    int j     = blockIdx.x * 256 + threadIdx.x;
    const float* Lp = g_L + (size_t)b * HW * HW + (size_t)chunk * CHUNK_I * HW + j;

    float m = -CUDART_INF_F;
    float s = 0.0f;
#pragma unroll 4
    for (int i = 0; i < CHUNK_I; i += 4) {
        float x0 = Lp[(size_t)(i + 0) * HW];
        float x1 = Lp[(size_t)(i + 1) * HW];
        float x2 = Lp[(size_t)(i + 2) * HW];
        float x3 = Lp[(size_t)(i + 3) * HW];
        float mx = fmaxf(fmaxf(x0, x1), fmaxf(x2, x3));
        if (mx > m) {
            s *= __expf(m - mx);
            m = mx;
        }
        s += __expf(x0 - m) + __expf(x1 - m) + __expf(x2 - m) + __expf(x3 - m);
    }
    int idx = (chunk * NB + b) * HW + j;
    g_pm[idx] = m;
    g_ps[idx] = s;
}

// ---------------------------------------------------------------------------
// Kernel 4b: combine partial col stats. One thread per (b, j).
// ---------------------------------------------------------------------------
__global__ void col_stats_combine_kernel() {
    int idx = blockIdx.x * 256 + threadIdx.x;   // b*HW + j
    if (idx >= NB * HW) return;
    int b = idx >> 10;
    int j = idx & (HW - 1);

    float mv[NCHUNK], sv[NCHUNK];
    float m = -CUDART_INF_F;
#pragma unroll
    for (int c = 0; c < NCHUNK; c++) {
        int p = (c * NB + b) * HW + j;
        mv[c] = g_pm[p];
        sv[c] = g_ps[p];
        m = fmaxf(m, mv[c]);
    }
    float s = 0.0f;
#pragma unroll
    for (int c = 0; c < NCHUNK; c++)
        s += sv[c] * __expf(mv[c] - m);

    g_cmax[idx] = m;
    g_cinv[idx] = 1.0f / s;
}

// ---------------------------------------------------------------------------
// Kernel 5: out[b][j][i] = exp(2L[i][j] - rmax[i] - cmax[j]) * rinv[i]*cinv[j]
// 32x32 smem tile transpose; coalesced read (j) and write (i).
// ---------------------------------------------------------------------------
__global__ void out_kernel(float* __restrict__ out) {
    __shared__ float s[32][33];
    int b  = blockIdx.z;
    int i0 = blockIdx.y * 32;
    int j0 = blockIdx.x * 32;
    int tx = threadIdx.x;   // 0..31
    int ty = threadIdx.y;   // 0..7

    const float* Lp = g_L + (size_t)b * HW * HW;
#pragma unroll
    for (int r = 0; r < 4; r++) {
        int il = ty + r * 8;
        s[il][tx] = Lp[(size_t)(i0 + il) * HW + j0 + tx];
    }
    __syncthreads();

    int i = i0 + tx;
    float rm = g_rmax[b * HW + i];
    float ri = g_rinv[b * HW + i];
    float* op = out + (size_t)b * HW * HW;
#pragma unroll
    for (int r = 0; r < 4; r++) {
        int jl = ty + r * 8;
        int j  = j0 + jl;
        float cm = g_cmax[b * HW + j];
        float ci = g_cinv[b * HW + j];
        float v  = __expf(2.0f * s[tx][jl] - rm - cm) * (ri * ci);
        op[(size_t)j * HW + i] = v;
    }
}

// ---------------------------------------------------------------------------
extern "C" void kernel_launch(void* const* d_in, const int* in_sizes, int n_in,
                              void* d_out, int out_size) {
    const float* A  = (const float*)d_in[0];  // feature_A [32,256,32,32]
    const float* Bf = (const float*)d_in[1];  // feature_B [32,256,32,32]
    float* out = (float*)d_out;               // [32,1024,32,32]

    transpose_planes_kernel<<<NB * NC, 256>>>(A);
    sgemm_kernel<<<dim3(8, 8, NB), 256>>>(Bf);
    row_stats_kernel<<<(NB * HW) / 8, 256>>>();
    col_stats_part_kernel<<<dim3(HW / 256, NCHUNK, NB), 256>>>();
    col_stats_combine_kernel<<<(NB * HW + 255) / 256, 256>>>();
    out_kernel<<<dim3(32, 32, NB), dim3(32, 8)>>>(out);
}

// round 5
// speedup vs baseline: 1.3662x; 1.1871x over previous
#include <cuda_runtime.h>
#include <math_constants.h>
#include <cstdint>

#define NB 32
#define NC 256
#define HW 1024
#define NCHUNK 8
#define CHUNK_I (HW / NCHUNK)

static __device__ __constant__ float c_invT = 14.2857142857142857f; // 1/0.07

// Fragment-ordered operands (tf32 values stored as f32 bits)
// M-side (feature_B, GEMM-A): [b][it16 64][kt8 32][lane 32][reg 4]
// N-side (feature_A*invT, GEMM-B): [b][jt8 128][kt8 32][lane 32][reg 2]
__device__ float g_MhiP[(size_t)NB * 64 * 32 * 128];
__device__ float g_MloP[(size_t)NB * 64 * 32 * 128];
__device__ float g_NhiP[(size_t)NB * 128 * 32 * 64];
__device__ float g_NloP[(size_t)NB * 128 * 32 * 64];
__device__ float g_L[(size_t)NB * HW * HW];
__device__ float g_rmax[NB * HW];
__device__ float g_rinv[NB * HW];
__device__ float g_cmax[NB * HW];
__device__ float g_cinv[NB * HW];
__device__ float g_pm[NCHUNK * NB * HW];
__device__ float g_ps[NCHUNK * NB * HW];

// ---- helpers --------------------------------------------------------------
// cvt.rna.tf32.f32 writes a .b32 destination (fp32-formatted, mantissa tail 0)
__device__ __forceinline__ float tf32_rna(float x) {
    uint32_t r;
    asm("cvt.rna.tf32.f32 %0, %1;" : "=r"(r) : "f"(x));
    return __uint_as_float(r);
}
__device__ __forceinline__ uint32_t smem_u32(const void* p) {
    uint32_t a;
    asm("{ .reg .u64 t; cvta.to.shared.u64 t, %1; cvt.u32.u64 %0, t; }"
        : "=r"(a) : "l"(p));
    return a;
}
__device__ __forceinline__ void cp16(uint32_t sdst, const float* gsrc) {
    asm volatile("cp.async.cg.shared.global [%0], [%1], 16;"
                 :: "r"(sdst), "l"(gsrc) : "memory");
}
__device__ __forceinline__ void cp_commit() {
    asm volatile("cp.async.commit_group;" ::: "memory");
}
template <int N>
__device__ __forceinline__ void cp_wait() {
    asm volatile("cp.async.wait_group %0;" :: "n"(N) : "memory");
}

__device__ __forceinline__ void mma_tf32(float c[4], const uint32_t a[4],
                                         const uint32_t b[2]) {
    asm volatile(
        "mma.sync.aligned.m16n8k8.row.col.f32.tf32.tf32.f32 "
        "{%0,%1,%2,%3}, {%4,%5,%6,%7}, {%8,%9}, {%0,%1,%2,%3};"
        : "+f"(c[0]), "+f"(c[1]), "+f"(c[2]), "+f"(c[3])
        : "r"(a[0]), "r"(a[1]), "r"(a[2]), "r"(a[3]), "r"(b[0]), "r"(b[1]));
}

// ---------------------------------------------------------------------------
// Kernel 1: split + repack into HMMA fragment order.
// Input tile: 32 channels x 32 hw positions. Both sides natural hw order.
// grid: (hw/32, c/32, 2*NB), block 256
// ---------------------------------------------------------------------------
__global__ void split_frag_kernel(const float* __restrict__ A,
                                  const float* __restrict__ Bf) {
    __shared__ float s[32][33];
    int zb   = blockIdx.z;          // side*NB + b
    int side = zb >> 5;
    int b    = zb & 31;
    int c0   = blockIdx.y * 32;
    int hw0  = blockIdx.x * 32;
    const float* src = (side ? A : Bf) + (size_t)b * NC * HW;
    int t    = threadIdx.x;
    int lane = t & 31;
    int g    = lane >> 2;
    int tig  = lane & 3;
    {
        int cr0 = t >> 5;
#pragma unroll
        for (int r = 0; r < 4; r++) {
            int cr = cr0 + r * 8;
            s[cr][lane] = src[(size_t)(c0 + cr) * HW + hw0 + lane];
        }
    }
    __syncthreads();

    if (side == 0) {
        // M-side: 8 blocks of (it_l in 0..1, kt_l in 0..3), 4 regs each
        int blk  = t >> 5;
        int it_l = blk >> 2;
        int kt_l = blk & 3;
        float hi[4], lo[4];
#pragma unroll
        for (int r = 0; r < 4; r++) {
            int row = it_l * 16 + g + 8 * (r & 1);
            int k   = kt_l * 8 + tig + 4 * (r >> 1);
            float v = s[k][row];
            hi[r] = tf32_rna(v);
            lo[r] = tf32_rna(v - hi[r]);
        }
        int it_g = (hw0 >> 4) + it_l;
        int kt_g = (c0 >> 3) + kt_l;
        size_t o = (((size_t)b * 64 + it_g) * 32 + kt_g) * 128 + lane * 4;
        *(float4*)(g_MhiP + o) = make_float4(hi[0], hi[1], hi[2], hi[3]);
        *(float4*)(g_MloP + o) = make_float4(lo[0], lo[1], lo[2], lo[3]);
    } else {
        // N-side: 16 blocks of (jt_l 0..3, kt_l 0..3), 2 regs each; 2 blocks/thread
        int bb = t >> 5;
#pragma unroll
        for (int h = 0; h < 2; h++) {
            int blk  = bb + h * 8;
            int jt_l = blk & 3;
            int kt_l = blk >> 2;
            float hi[2], lo[2];
#pragma unroll
            for (int r = 0; r < 2; r++) {
                int row = jt_l * 8 + g;
                int k   = kt_l * 8 + tig + 4 * r;
                float v = s[k][row] * c_invT;
                hi[r] = tf32_rna(v);
                lo[r] = tf32_rna(v - hi[r]);
            }
            int jt_g = (hw0 >> 3) + jt_l;
            int kt_g = (c0 >> 3) + kt_l;
            size_t o = (((size_t)b * 128 + jt_g) * 32 + kt_g) * 64 + lane * 2;
            *(float2*)(g_NhiP + o) = make_float2(hi[0], hi[1]);
            *(float2*)(g_NloP + o) = make_float2(lo[0], lo[1]);
        }
    }
}

// ---------------------------------------------------------------------------
// Kernel 2: TF32 split GEMM on warp-level mma.sync (HMMA).
// L[b][i][j] = sum over K'=768 of M'(i,k') N'(j,k'), term-blocked.
// CTA 128x128, 8 warps (4 m x 2 n), warp tile 32x64, K-chunk 32, 24 chunks.
// ---------------------------------------------------------------------------
#define ACH_F 4096                 // A floats per chunk (8 it x 4 kt x 128)
#define BCH_F 4096                 // B floats per chunk (16 jt x 4 kt x 64)
#define STG_F (ACH_F + BCH_F)      // 8192 floats = 32KB per stage
#define GEMM_SMEM (2 * STG_F * 4)  // 65536 bytes

__device__ __forceinline__ void gemm_copy_chunk(uint32_t sA, uint32_t sB,
                                                const float* gA, const float* gB,
                                                int t) {
#pragma unroll
    for (int q = 0; q < 4; q++) {
        int f4 = q * 256 + t;
        int it = f4 >> 7, rema = f4 & 127;
        cp16(sA + (uint32_t)f4 * 16, gA + (size_t)it * 4096 + rema * 4);
        int jt = f4 >> 6, remb = f4 & 63;
        cp16(sB + (uint32_t)f4 * 16, gB + (size_t)jt * 2048 + remb * 4);
    }
    cp_commit();
}

__global__ void __launch_bounds__(256) gemm_hmma_kernel() {
    extern __shared__ float sm[];
    uint32_t sbase = smem_u32(sm);
    int b   = blockIdx.z;
    int jt0 = blockIdx.x * 16;     // j0 = bx*128
    int it0 = blockIdx.y * 8;      // i0 = by*128
    int t    = threadIdx.x;
    int wid  = t >> 5;
    int lane = t & 31;
    int wm   = wid >> 1;           // 0..3
    int wn   = wid & 1;            // 0..1
    int g    = lane >> 2;
    int tig  = lane & 3;

    const float* MhiB = g_MhiP + ((size_t)b * 64 + it0) * 32 * 128;
    const float* MloB = g_MloP + ((size_t)b * 64 + it0) * 32 * 128;
    const float* NhiB = g_NhiP + ((size_t)b * 128 + jt0) * 32 * 64;
    const float* NloB = g_NloP + ((size_t)b * 128 + jt0) * 32 * 64;

    float acc[2][8][4];
#pragma unroll
    for (int m = 0; m < 2; m++)
#pragma unroll
        for (int n = 0; n < 8; n++)
#pragma unroll
            for (int r = 0; r < 4; r++) acc[m][n][r] = 0.0f;

    // chunk c: term = c>>3 (0:hi*hi 1:hi*lo 2:lo*hi), kt offset (c&7)*4
    const float* gA;
    const float* gB;
#define CHUNK_PTRS(c)                                                       \
    {                                                                       \
        int term = (c) >> 3;                                                \
        int ko   = ((c) & 7) * 4;                                           \
        gA = (term == 2 ? MloB : MhiB) + (size_t)ko * 128;                  \
        gB = (term == 1 ? NloB : NhiB) + (size_t)ko * 64;                   \
    }

    CHUNK_PTRS(0);
    gemm_copy_chunk(sbase, sbase + ACH_F * 4, gA, gB, t);

    for (int c = 0; c < 24; c++) {
        int stage = c & 1;
        if (c + 1 < 24) {
            int ns = (c + 1) & 1;
            CHUNK_PTRS(c + 1);
            gemm_copy_chunk(sbase + ns * STG_F * 4,
                            sbase + (ns * STG_F + ACH_F) * 4, gA, gB, t);
            cp_wait<1>();
        } else {
            cp_wait<0>();
        }
        __syncthreads();

        const float* sA = sm + stage * STG_F;
        const float* sB = sA + ACH_F;
#pragma unroll
        for (int kt = 0; kt < 4; kt++) {
            uint32_t a[2][4];
#pragma unroll
            for (int m = 0; m < 2; m++) {
                int it = wm * 2 + m;
                float4 v = *(const float4*)(sA + it * 512 + kt * 128 + lane * 4);
                a[m][0] = __float_as_uint(v.x);
                a[m][1] = __float_as_uint(v.y);
                a[m][2] = __float_as_uint(v.z);
                a[m][3] = __float_as_uint(v.w);
            }
            uint32_t bf[8][2];
#pragma unroll
            for (int n = 0; n < 8; n++) {
                int jt = wn * 8 + n;
                float2 v = *(const float2*)(sB + jt * 256 + kt * 64 + lane * 2);
                bf[n][0] = __float_as_uint(v.x);
                bf[n][1] = __float_as_uint(v.y);
            }
#pragma unroll
            for (int m = 0; m < 2; m++)
#pragma unroll
                for (int n = 0; n < 8; n++)
                    mma_tf32(acc[m][n], a[m], bf[n]);
        }
        __syncthreads();
    }

    // Epilogue: c0/c1 -> (row g, cols 2tig..), c2/c3 -> (row g+8)
    float* Lp = g_L + (size_t)b * HW * HW;
    int j0 = jt0 * 8;
    int i0 = it0 * 16;
#pragma unroll
    for (int m = 0; m < 2; m++) {
        int row0 = i0 + (wm * 2 + m) * 16 + g;
#pragma unroll
        for (int n = 0; n < 8; n++) {
            int col = j0 + (wn * 8 + n) * 8 + tig * 2;
            *(float2*)(Lp + (size_t)row0 * HW + col) =
                make_float2(acc[m][n][0], acc[m][n][1]);
            *(float2*)(Lp + (size_t)(row0 + 8) * HW + col) =
                make_float2(acc[m][n][2], acc[m][n][3]);
        }
    }
}

// ---------------------------------------------------------------------------
// Kernel 3: row stats (reduce over j, contiguous). One warp per row.
// ---------------------------------------------------------------------------
__global__ void row_stats_kernel() {
    int gw   = (blockIdx.x * blockDim.x + threadIdx.x) >> 5;
    int lane = threadIdx.x & 31;
    if (gw >= NB * HW) return;
    const float* row = g_L + (size_t)gw * HW;

    float m = -CUDART_INF_F;
#pragma unroll
    for (int it = 0; it < 8; it++) {
        float4 x = *(const float4*)(row + it * 128 + lane * 4);
        m = fmaxf(m, fmaxf(fmaxf(x.x, x.y), fmaxf(x.z, x.w)));
    }
#pragma unroll
    for (int off = 16; off > 0; off >>= 1)
        m = fmaxf(m, __shfl_xor_sync(0xFFFFFFFFu, m, off));

    float s = 0.0f;
#pragma unroll
    for (int it = 0; it < 8; it++) {
        float4 x = *(const float4*)(row + it * 128 + lane * 4);
        s += __expf(x.x - m) + __expf(x.y - m) + __expf(x.z - m) + __expf(x.w - m);
    }
#pragma unroll
    for (int off = 16; off > 0; off >>= 1)
        s += __shfl_xor_sync(0xFFFFFFFFu, s, off);

    if (lane == 0) {
        g_rmax[gw] = m;
        g_rinv[gw] = 1.0f / s;
    }
}

// ---------------------------------------------------------------------------
// Kernel 4a/4b: col stats (partial + combine), natural j index.
// ---------------------------------------------------------------------------
__global__ void col_stats_part_kernel() {
    int b     = blockIdx.z;
    int chunk = blockIdx.y;
    int j     = blockIdx.x * 256 + threadIdx.x;
    const float* Lp = g_L + (size_t)b * HW * HW + (size_t)chunk * CHUNK_I * HW + j;

    float m = -CUDART_INF_F;
    float s = 0.0f;
#pragma unroll 4
    for (int i = 0; i < CHUNK_I; i += 4) {
        float x0 = Lp[(size_t)(i + 0) * HW];
        float x1 = Lp[(size_t)(i + 1) * HW];
        float x2 = Lp[(size_t)(i + 2) * HW];
        float x3 = Lp[(size_t)(i + 3) * HW];
        float mx = fmaxf(fmaxf(x0, x1), fmaxf(x2, x3));
        if (mx > m) { s *= __expf(m - mx); m = mx; }
        s += __expf(x0 - m) + __expf(x1 - m) + __expf(x2 - m) + __expf(x3 - m);
    }
    int idx = (chunk * NB + b) * HW + j;
    g_pm[idx] = m;
    g_ps[idx] = s;
}

__global__ void col_stats_combine_kernel() {
    int idx = blockIdx.x * 256 + threadIdx.x;
    if (idx >= NB * HW) return;
    int b = idx >> 10;
    int j = idx & (HW - 1);

    float mv[NCHUNK], sv[NCHUNK];
    float m = -CUDART_INF_F;
#pragma unroll
    for (int c = 0; c < NCHUNK; c++) {
        int p = (c * NB + b) * HW + j;
        mv[c] = g_pm[p];
        sv[c] = g_ps[p];
        m = fmaxf(m, mv[c]);
    }
    float s = 0.0f;
#pragma unroll
    for (int c = 0; c < NCHUNK; c++)
        s += sv[c] * __expf(mv[c] - m);

    g_cmax[idx] = m;
    g_cinv[idx] = 1.0f / s;
}

// ---------------------------------------------------------------------------
// Kernel 5: out[b][perm(j')][i] = exp(2L[i][j'] - rmax[i] - cmax[j']) * rinv*cinv
// perm(j') = (j'%32)*32 + j'/32  (the (w,h) flatten of feature_A)
// ---------------------------------------------------------------------------
__global__ void out_kernel(float* __restrict__ out) {
    __shared__ float s[32][33];
    int b  = blockIdx.z;
    int i0 = blockIdx.y * 32;
    int j0 = blockIdx.x * 32;
    int tx = threadIdx.x;
    int ty = threadIdx.y;

    const float* Lp = g_L + (size_t)b * HW * HW;
#pragma unroll
    for (int r = 0; r < 4; r++) {
        int il = ty + r * 8;
        s[il][tx] = Lp[(size_t)(i0 + il) * HW + j0 + tx];
    }
    __syncthreads();

    int i = i0 + tx;
    float rm = g_rmax[b * HW + i];
    float ri = g_rinv[b * HW + i];
    float* op = out + (size_t)b * HW * HW;
#pragma unroll
    for (int r = 0; r < 4; r++) {
        int jl = ty + r * 8;
        int jn = j0 + jl;                                // natural j'
        float cm = g_cmax[b * HW + jn];
        float ci = g_cinv[b * HW + jn];
        float v  = __expf(2.0f * s[tx][jl] - rm - cm) * (ri * ci);
        int j = ((jn & 31) << 5) | (jn >> 5);            // output permutation
        op[(size_t)j * HW + i] = v;
    }
}

// ---------------------------------------------------------------------------
extern "C" void kernel_launch(void* const* d_in, const int* in_sizes, int n_in,
                              void* d_out, int out_size) {
    const float* A  = (const float*)d_in[0];  // feature_A [32,256,32,32]
    const float* Bf = (const float*)d_in[1];  // feature_B [32,256,32,32]
    float* out = (float*)d_out;               // [32,1024,32,32]

    static int smem_set = 0;
    if (!smem_set) {
        cudaFuncSetAttribute(gemm_hmma_kernel,
                             cudaFuncAttributeMaxDynamicSharedMemorySize,
                             GEMM_SMEM);
        smem_set = 1;
    }

    split_frag_kernel<<<dim3(32, 8, 2 * NB), 256>>>(A, Bf);
    gemm_hmma_kernel<<<dim3(8, 8, NB), 256, GEMM_SMEM>>>();
    row_stats_kernel<<<(NB * HW) / 8, 256>>>();
    col_stats_part_kernel<<<dim3(HW / 256, NCHUNK, NB), 256>>>();
    col_stats_combine_kernel<<<(NB * HW + 255) / 256, 256>>>();
    out_kernel<<<dim3(32, 32, NB), dim3(32, 8)>>>(out);
}

// round 6
// speedup vs baseline: 1.4830x; 1.0855x over previous
#include <cuda_runtime.h>
#include <math_constants.h>
#include <cstdint>

#define NB 32
#define NC 256
#define HW 1024
#define NRP 16          // row-partial slices (8 j-blocks x 2 wn)
#define NCP 32          // col-partial slices (8 i-blocks x 4 wm)

static __device__ __constant__ float c_invT = 14.2857142857142857f; // 1/0.07

// Fragment-ordered operands (tf32 values stored as f32 bits)
__device__ float g_MhiP[(size_t)NB * 64 * 32 * 128];
__device__ float g_MloP[(size_t)NB * 64 * 32 * 128];
__device__ float g_NhiP[(size_t)NB * 128 * 32 * 64];
__device__ float g_NloP[(size_t)NB * 128 * 32 * 64];
__device__ float g_L[(size_t)NB * HW * HW];
__device__ float g_rmax[NB * HW];
__device__ float g_rinv[NB * HW];
__device__ float g_cmax[NB * HW];
__device__ float g_cinv[NB * HW];
__device__ float g_prm[(size_t)NRP * NB * HW];   // row partial max
__device__ float g_prs[(size_t)NRP * NB * HW];   // row partial sumexp
__device__ float g_pcm[(size_t)NCP * NB * HW];   // col partial max
__device__ float g_pcs[(size_t)NCP * NB * HW];   // col partial sumexp

// ---- helpers --------------------------------------------------------------
__device__ __forceinline__ float tf32_rna(float x) {
    uint32_t r;
    asm("cvt.rna.tf32.f32 %0, %1;" : "=r"(r) : "f"(x));
    return __uint_as_float(r);
}
__device__ __forceinline__ uint32_t smem_u32(const void* p) {
    uint32_t a;
    asm("{ .reg .u64 t; cvta.to.shared.u64 t, %1; cvt.u32.u64 %0, t; }"
        : "=r"(a) : "l"(p));
    return a;
}
__device__ __forceinline__ void cp16(uint32_t sdst, const float* gsrc) {
    asm volatile("cp.async.cg.shared.global [%0], [%1], 16;"
                 :: "r"(sdst), "l"(gsrc) : "memory");
}
__device__ __forceinline__ void cp_commit() {
    asm volatile("cp.async.commit_group;" ::: "memory");
}
template <int N>
__device__ __forceinline__ void cp_wait() {
    asm volatile("cp.async.wait_group %0;" :: "n"(N) : "memory");
}

__device__ __forceinline__ void mma_tf32(float c[4], const uint32_t a[4],
                                         const uint32_t b[2]) {
    asm volatile(
        "mma.sync.aligned.m16n8k8.row.col.f32.tf32.tf32.f32 "
        "{%0,%1,%2,%3}, {%4,%5,%6,%7}, {%8,%9}, {%0,%1,%2,%3};"
        : "+f"(c[0]), "+f"(c[1]), "+f"(c[2]), "+f"(c[3])
        : "r"(a[0]), "r"(a[1]), "r"(a[2]), "r"(a[3]), "r"(b[0]), "r"(b[1]));
}

// ---------------------------------------------------------------------------
// Kernel 1: split + repack into HMMA fragment order.
// ---------------------------------------------------------------------------
__global__ void split_frag_kernel(const float* __restrict__ A,
                                  const float* __restrict__ Bf) {
    __shared__ float s[32][33];
    int zb   = blockIdx.z;          // side*NB + b
    int side = zb >> 5;
    int b    = zb & 31;
    int c0   = blockIdx.y * 32;
    int hw0  = blockIdx.x * 32;
    const float* src = (side ? A : Bf) + (size_t)b * NC * HW;
    int t    = threadIdx.x;
    int lane = t & 31;
    int g    = lane >> 2;
    int tig  = lane & 3;
    {
        int cr0 = t >> 5;
#pragma unroll
        for (int r = 0; r < 4; r++) {
            int cr = cr0 + r * 8;
            s[cr][lane] = src[(size_t)(c0 + cr) * HW + hw0 + lane];
        }
    }
    __syncthreads();

    if (side == 0) {
        int blk  = t >> 5;
        int it_l = blk >> 2;
        int kt_l = blk & 3;
        float hi[4], lo[4];
#pragma unroll
        for (int r = 0; r < 4; r++) {
            int row = it_l * 16 + g + 8 * (r & 1);
            int k   = kt_l * 8 + tig + 4 * (r >> 1);
            float v = s[k][row];
            hi[r] = tf32_rna(v);
            lo[r] = tf32_rna(v - hi[r]);
        }
        int it_g = (hw0 >> 4) + it_l;
        int kt_g = (c0 >> 3) + kt_l;
        size_t o = (((size_t)b * 64 + it_g) * 32 + kt_g) * 128 + lane * 4;
        *(float4*)(g_MhiP + o) = make_float4(hi[0], hi[1], hi[2], hi[3]);
        *(float4*)(g_MloP + o) = make_float4(lo[0], lo[1], lo[2], lo[3]);
    } else {
        int bb = t >> 5;
#pragma unroll
        for (int h = 0; h < 2; h++) {
            int blk  = bb + h * 8;
            int jt_l = blk & 3;
            int kt_l = blk >> 2;
            float hi[2], lo[2];
#pragma unroll
            for (int r = 0; r < 2; r++) {
                int row = jt_l * 8 + g;
                int k   = kt_l * 8 + tig + 4 * r;
                float v = s[k][row] * c_invT;
                hi[r] = tf32_rna(v);
                lo[r] = tf32_rna(v - hi[r]);
            }
            int jt_g = (hw0 >> 3) + jt_l;
            int kt_g = (c0 >> 3) + kt_l;
            size_t o = (((size_t)b * 128 + jt_g) * 32 + kt_g) * 64 + lane * 2;
            *(float2*)(g_NhiP + o) = make_float2(hi[0], hi[1]);
            *(float2*)(g_NloP + o) = make_float2(lo[0], lo[1]);
        }
    }
}

// ---------------------------------------------------------------------------
// Kernel 2: TF32 split GEMM on mma.sync + fused partial softmax stats.
// ---------------------------------------------------------------------------
#define ACH_F 4096
#define BCH_F 4096
#define STG_F (ACH_F + BCH_F)
#define GEMM_SMEM (2 * STG_F * 4)

__device__ __forceinline__ void gemm_copy_chunk(uint32_t sA, uint32_t sB,
                                                const float* gA, const float* gB,
                                                int t) {
#pragma unroll
    for (int q = 0; q < 4; q++) {
        int f4 = q * 256 + t;
        int it = f4 >> 7, rema = f4 & 127;
        cp16(sA + (uint32_t)f4 * 16, gA + (size_t)it * 4096 + rema * 4);
        int jt = f4 >> 6, remb = f4 & 63;
        cp16(sB + (uint32_t)f4 * 16, gB + (size_t)jt * 2048 + remb * 4);
    }
    cp_commit();
}

__global__ void __launch_bounds__(256) gemm_hmma_kernel() {
    extern __shared__ float sm[];
    uint32_t sbase = smem_u32(sm);
    int b   = blockIdx.z;
    int jt0 = blockIdx.x * 16;     // j0 = bx*128
    int it0 = blockIdx.y * 8;      // i0 = by*128
    int t    = threadIdx.x;
    int wid  = t >> 5;
    int lane = t & 31;
    int wm   = wid >> 1;
    int wn   = wid & 1;
    int g    = lane >> 2;
    int tig  = lane & 3;

    const float* MhiB = g_MhiP + ((size_t)b * 64 + it0) * 32 * 128;
    const float* MloB = g_MloP + ((size_t)b * 64 + it0) * 32 * 128;
    const float* NhiB = g_NhiP + ((size_t)b * 128 + jt0) * 32 * 64;
    const float* NloB = g_NloP + ((size_t)b * 128 + jt0) * 32 * 64;

    float acc[2][8][4];
#pragma unroll
    for (int m = 0; m < 2; m++)
#pragma unroll
        for (int n = 0; n < 8; n++)
#pragma unroll
            for (int r = 0; r < 4; r++) acc[m][n][r] = 0.0f;

    const float* gA;
    const float* gB;
#define CHUNK_PTRS(c)                                                       \
    {                                                                       \
        int term = (c) >> 3;                                                \
        int ko   = ((c) & 7) * 4;                                           \
        gA = (term == 2 ? MloB : MhiB) + (size_t)ko * 128;                  \
        gB = (term == 1 ? NloB : NhiB) + (size_t)ko * 64;                   \
    }

    CHUNK_PTRS(0);
    gemm_copy_chunk(sbase, sbase + ACH_F * 4, gA, gB, t);

    for (int c = 0; c < 24; c++) {
        int stage = c & 1;
        if (c + 1 < 24) {
            int ns = (c + 1) & 1;
            CHUNK_PTRS(c + 1);
            gemm_copy_chunk(sbase + ns * STG_F * 4,
                            sbase + (ns * STG_F + ACH_F) * 4, gA, gB, t);
            cp_wait<1>();
        } else {
            cp_wait<0>();
        }
        __syncthreads();

        const float* sA = sm + stage * STG_F;
        const float* sB = sA + ACH_F;
#pragma unroll
        for (int kt = 0; kt < 4; kt++) {
            uint32_t a[2][4];
#pragma unroll
            for (int m = 0; m < 2; m++) {
                int it = wm * 2 + m;
                float4 v = *(const float4*)(sA + it * 512 + kt * 128 + lane * 4);
                a[m][0] = __float_as_uint(v.x);
                a[m][1] = __float_as_uint(v.y);
                a[m][2] = __float_as_uint(v.z);
                a[m][3] = __float_as_uint(v.w);
            }
            uint32_t bf[8][2];
#pragma unroll
            for (int n = 0; n < 8; n++) {
                int jt = wn * 8 + n;
                float2 v = *(const float2*)(sB + jt * 256 + kt * 64 + lane * 2);
                bf[n][0] = __float_as_uint(v.x);
                bf[n][1] = __float_as_uint(v.y);
            }
#pragma unroll
            for (int m = 0; m < 2; m++)
#pragma unroll
                for (int n = 0; n < 8; n++)
                    mma_tf32(acc[m][n], a[m], bf[n]);
        }
        __syncthreads();
    }

    // ---- store L tile ----
    float* Lp = g_L + (size_t)b * HW * HW;
    int j0 = jt0 * 8;
    int i0 = it0 * 16;
#pragma unroll
    for (int m = 0; m < 2; m++) {
        int row0 = i0 + (wm * 2 + m) * 16 + g;
#pragma unroll
        for (int n = 0; n < 8; n++) {
            int col = j0 + (wn * 8 + n) * 8 + tig * 2;
            *(float2*)(Lp + (size_t)row0 * HW + col) =
                make_float2(acc[m][n][0], acc[m][n][1]);
            *(float2*)(Lp + (size_t)(row0 + 8) * HW + col) =
                make_float2(acc[m][n][2], acc[m][n][3]);
        }
    }

    // ---- fused row partials (over this warp's 64 j's) ----
    // row slot (m, rp): local row = wm*32 + m*16 + rp*8 + g
    int rslice = blockIdx.x * 2 + wn;       // 0..15
#pragma unroll
    for (int m = 0; m < 2; m++)
#pragma unroll
        for (int rp = 0; rp < 2; rp++) {
            float rm = -CUDART_INF_F;
#pragma unroll
            for (int n = 0; n < 8; n++)
                rm = fmaxf(rm, fmaxf(acc[m][n][rp * 2], acc[m][n][rp * 2 + 1]));
            rm = fmaxf(rm, __shfl_xor_sync(0xFFFFFFFFu, rm, 1));
            rm = fmaxf(rm, __shfl_xor_sync(0xFFFFFFFFu, rm, 2));
            float rs = 0.0f;
#pragma unroll
            for (int n = 0; n < 8; n++)
                rs += __expf(acc[m][n][rp * 2] - rm) +
                      __expf(acc[m][n][rp * 2 + 1] - rm);
            rs += __shfl_xor_sync(0xFFFFFFFFu, rs, 1);
            rs += __shfl_xor_sync(0xFFFFFFFFu, rs, 2);
            if (tig == 0) {
                int i = i0 + wm * 32 + m * 16 + rp * 8 + g;
                size_t idx = (size_t)rslice * NB * HW + b * HW + i;
                g_prm[idx] = rm;
                g_prs[idx] = rs;
            }
        }

    // ---- fused col partials (over this warp's 32 i's) ----
    // col slot (n, q): j = j0 + wn*64 + n*8 + tig*2 + q
    int cslice = blockIdx.y * 4 + wm;       // 0..31
#pragma unroll
    for (int n = 0; n < 8; n++)
#pragma unroll
        for (int q = 0; q < 2; q++) {
            float cm = fmaxf(fmaxf(acc[0][n][q], acc[0][n][2 + q]),
                             fmaxf(acc[1][n][q], acc[1][n][2 + q]));
            cm = fmaxf(cm, __shfl_xor_sync(0xFFFFFFFFu, cm, 4));
            cm = fmaxf(cm, __shfl_xor_sync(0xFFFFFFFFu, cm, 8));
            cm = fmaxf(cm, __shfl_xor_sync(0xFFFFFFFFu, cm, 16));
            float cs = __expf(acc[0][n][q] - cm) + __expf(acc[0][n][2 + q] - cm) +
                       __expf(acc[1][n][q] - cm) + __expf(acc[1][n][2 + q] - cm);
            cs += __shfl_xor_sync(0xFFFFFFFFu, cs, 4);
            cs += __shfl_xor_sync(0xFFFFFFFFu, cs, 8);
            cs += __shfl_xor_sync(0xFFFFFFFFu, cs, 16);
            if (g == 0) {
                int j = j0 + wn * 64 + n * 8 + tig * 2 + q;
                size_t idx = (size_t)cslice * NB * HW + b * HW + j;
                g_pcm[idx] = cm;
                g_pcs[idx] = cs;
            }
        }
}

// ---------------------------------------------------------------------------
// Kernel 3: combine row partials (16-way). One thread per (b,i).
// ---------------------------------------------------------------------------
__global__ void row_combine_kernel() {
    int idx = blockIdx.x * 256 + threadIdx.x;   // b*HW + i
    if (idx >= NB * HW) return;
    float m = -CUDART_INF_F;
    float mv[NRP], sv[NRP];
#pragma unroll
    for (int p = 0; p < NRP; p++) {
        mv[p] = g_prm[(size_t)p * NB * HW + idx];
        sv[p] = g_prs[(size_t)p * NB * HW + idx];
        m = fmaxf(m, mv[p]);
    }
    float s = 0.0f;
#pragma unroll
    for (int p = 0; p < NRP; p++)
        s += sv[p] * __expf(mv[p] - m);
    g_rmax[idx] = m;
    g_rinv[idx] = 1.0f / s;
}

// ---------------------------------------------------------------------------
// Kernel 4: combine col partials (32-way). One thread per (b,j).
// ---------------------------------------------------------------------------
__global__ void col_combine_kernel() {
    int idx = blockIdx.x * 256 + threadIdx.x;   // b*HW + j
    if (idx >= NB * HW) return;
    float m = -CUDART_INF_F;
    float mv[NCP], sv[NCP];
#pragma unroll
    for (int p = 0; p < NCP; p++) {
        mv[p] = g_pcm[(size_t)p * NB * HW + idx];
        sv[p] = g_pcs[(size_t)p * NB * HW + idx];
        m = fmaxf(m, mv[p]);
    }
    float s = 0.0f;
#pragma unroll
    for (int p = 0; p < NCP; p++)
        s += sv[p] * __expf(mv[p] - m);
    g_cmax[idx] = m;
    g_cinv[idx] = 1.0f / s;
}

// ---------------------------------------------------------------------------
// Kernel 5: out[b][perm(j')][i] = exp(2L[i][j'] - rmax[i] - cmax[j']) * rinv*cinv
// perm(j') = (j'%32)*32 + j'/32
// ---------------------------------------------------------------------------
__global__ void out_kernel(float* __restrict__ out) {
    __shared__ float s[32][33];
    int b  = blockIdx.z;
    int i0 = blockIdx.y * 32;
    int j0 = blockIdx.x * 32;
    int tx = threadIdx.x;
    int ty = threadIdx.y;

    const float* Lp = g_L + (size_t)b * HW * HW;
#pragma unroll
    for (int r = 0; r < 4; r++) {
        int il = ty + r * 8;
        s[il][tx] = Lp[(size_t)(i0 + il) * HW + j0 + tx];
    }
    __syncthreads();

    int i = i0 + tx;
    float rm = g_rmax[b * HW + i];
    float ri = g_rinv[b * HW + i];
    float* op = out + (size_t)b * HW * HW;
#pragma unroll
    for (int r = 0; r < 4; r++) {
        int jl = ty + r * 8;
        int jn = j0 + jl;
        float cm = g_cmax[b * HW + jn];
        float ci = g_cinv[b * HW + jn];
        float v  = __expf(2.0f * s[tx][jl] - rm - cm) * (ri * ci);
        int j = ((jn & 31) << 5) | (jn >> 5);
        op[(size_t)j * HW + i] = v;
    }
}

// ---------------------------------------------------------------------------
extern "C" void kernel_launch(void* const* d_in, const int* in_sizes, int n_in,
                              void* d_out, int out_size) {
    const float* A  = (const float*)d_in[0];  // feature_A [32,256,32,32]
    const float* Bf = (const float*)d_in[1];  // feature_B [32,256,32,32]
    float* out = (float*)d_out;               // [32,1024,32,32]

    static int smem_set = 0;
    if (!smem_set) {
        cudaFuncSetAttribute(gemm_hmma_kernel,
                             cudaFuncAttributeMaxDynamicSharedMemorySize,
                             GEMM_SMEM);
        smem_set = 1;
    }

    split_frag_kernel<<<dim3(32, 8, 2 * NB), 256>>>(A, Bf);
    gemm_hmma_kernel<<<dim3(8, 8, NB), 256, GEMM_SMEM>>>();
    row_combine_kernel<<<(NB * HW + 255) / 256, 256>>>();
    col_combine_kernel<<<(NB * HW + 255) / 256, 256>>>();
    out_kernel<<<dim3(32, 32, NB), dim3(32, 8)>>>(out);
}